// round 11
// baseline (speedup 1.0000x reference)
#include <cuda_runtime.h>

#define HID 50
#define JP  64          // padded hidden units -> 16 warps of 8 j
#define K4N 13          // k padded 50->52, 4 per float4
#define BT  16
#define NTHREADS 512    // 16 warps, 4/SMSP
#define HBUF_F4 (K4N * 2 * 8)   // [k4][parity][8] float4

typedef unsigned long long u64;

__device__ __forceinline__ void ffma2(u64& d, u64 a, u64 b) {
    asm("fma.rn.f32x2 %0, %1, %2, %3;" : "=l"(d) : "l"(a), "l"(b), "l"(d));
}
__device__ __forceinline__ float f2lo(u64 a) { return __uint_as_float((unsigned)a); }
__device__ __forceinline__ float f2hi(u64 a) { return __uint_as_float((unsigned)(a >> 32)); }

__device__ __forceinline__ float tanh_a(float x) {
    float r;
    asm("tanh.approx.f32 %0, %1;" : "=f"(r) : "f"(x));
    return r;
}
__device__ __forceinline__ float sigmoid_a(float x) {
    return fmaf(0.5f, tanh_a(0.5f * x), 0.5f);
}

__global__ void __launch_bounds__(NTHREADS, 1)
seq2seq_kernel(const float* __restrict__ source,
               const float* __restrict__ eWih, const float* __restrict__ eWhh,
               const float* __restrict__ eBih, const float* __restrict__ eBhh,
               const float* __restrict__ dWih, const float* __restrict__ dWhh,
               const float* __restrict__ dBih, const float* __restrict__ dBhh,
               const float* __restrict__ fcW,  const float* __restrict__ fcB,
               float* __restrict__ out, int S, int T)
{
    extern __shared__ char smem_raw[];
    float4* wenc = (float4*)smem_raw;                 // [(k4*4+ty)*JP + j]
    float4* wdec = wenc + K4N * 4 * JP;
    float4* hbuf = wdec + K4N * 4 * JP;               // [2][k4][par][8]
    float*  xdec = (float*)(hbuf + 2 * HBUF_F4);      // [BT]
    float*  fcw  = xdec + BT;                         // [HID]
    float*  fcb  = fcw + HID;                         // [2]
    float*  srcsT = fcb + 2;                          // [S][BT]

    const int tid  = threadIdx.x;
    const int lane = tid & 31;
    const int wrp  = tid >> 5;                        // [0,16)
    const int b0g  = blockIdx.x * BT;

    // warp = (j-group of 8, batch-half); lane = (bp, jl): jl fastest -> dense wv
    const int jg = wrp & 7;                           // [0,8)
    const int bh = wrp >> 3;                          // {0,1}
    const int jl = lane & 7;
    const int bp = lane >> 3;                         // [0,4)
    const int j  = jg * 8 + jl;                       // [0,64)
    const int b0 = bh * 8 + bp * 2;                   // even row
    const int b1 = b0 + 1;                            // odd row
    const int hp = bh * 4 + bp;                       // index within parity plane

    // ---- stage weights: [k4][type][JP] float4 (4 k per float4)
    auto stage_w = [&](float4* dst, const float* Whh) {
        for (int idx = tid; idx < K4N * 4 * JP; idx += NTHREADS) {
            int k4 = idx / (4 * JP);
            int r  = idx % (4 * JP);
            int ty = r / JP, jj = r % JP;
            float4 v = make_float4(0.f, 0.f, 0.f, 0.f);
            if (jj < HID) {
                int row = ty * HID + jj;
                #pragma unroll
                for (int c = 0; c < 4; c++) {
                    int k = 4 * k4 + c;
                    if (k < HID) ((float*)&v)[c] = Whh[row * HID + k];
                }
            }
            dst[idx] = v;
        }
    };
    stage_w(wenc, eWhh);
    stage_w(wdec, dWhh);
    for (int i = tid; i < 2 * HBUF_F4; i += NTHREADS)
        hbuf[i] = make_float4(0.f, 0.f, 0.f, 0.f);
    if (tid < BT)  xdec[tid] = 0.f;
    if (tid < HID) fcw[tid] = fcW[tid];
    if (tid == 0)  fcb[0] = fcB[0];
    for (int idx = tid; idx < BT * S; idx += NTHREADS) {
        int bl = idx / S, t = idx % S;
        srcsT[t * BT + bl] = source[(size_t)(b0g + bl) * S + t];
    }

    // ---- per-thread constants / state
    float biasr[4], wihr[4];
    auto stage_c = [&](const float* Wih, const float* Bih, const float* Bhh) {
        #pragma unroll
        for (int ty = 0; ty < 4; ty++) {
            if (j < HID) {
                int row = ty * HID + j;
                biasr[ty] = Bih[row] + Bhh[row];
                wihr[ty]  = Wih[row];
            } else { biasr[ty] = 0.f; wihr[ty] = 0.f; }
        }
    };
    stage_c(eWih, eBih, eBhh);
    float c0 = 0.f, c1 = 0.f;
    __syncthreads();

    float g[8];  // gate pre-activations, index 2*ty + row-parity

    auto gemm = [&](const float4* wp, const float4* hb, float x0v, float x1v) {
        u64 a[8];
        #pragma unroll
        for (int ty = 0; ty < 4; ty++) {
            a[2 * ty]     = (u64)__float_as_uint(fmaf(x0v, wihr[ty], biasr[ty]));
            a[2 * ty + 1] = (u64)__float_as_uint(fmaf(x1v, wihr[ty], biasr[ty]));
        }
        const ulonglong2* w2 = (const ulonglong2*)wp;
        const ulonglong2* h2 = (const ulonglong2*)hb;
        #pragma unroll
        for (int k4 = 0; k4 < K4N; k4++) {
            ulonglong2 hv0 = h2[(k4 * 2 + 0) * 8 + hp];   // 4 distinct consec f4: dense 64B
            ulonglong2 hv1 = h2[(k4 * 2 + 1) * 8 + hp];
            #pragma unroll
            for (int ty = 0; ty < 4; ty++) {
                ulonglong2 wv = w2[(k4 * 4 + ty) * JP + j]; // 8 distinct consec f4: 128B
                ffma2(a[2 * ty],     wv.x, hv0.x);
                ffma2(a[2 * ty],     wv.y, hv0.y);
                ffma2(a[2 * ty + 1], wv.x, hv1.x);
                ffma2(a[2 * ty + 1], wv.y, hv1.y);
            }
        }
        #pragma unroll
        for (int i = 0; i < 8; i++) g[i] = f2lo(a[i]) + f2hi(a[i]);
    };

    // in-thread LSTM update: gates never leave registers
    auto update = [&](float* hnext) {
        {
            float iv = sigmoid_a(g[0]);
            float fv = sigmoid_a(g[2]);
            float gv = tanh_a(g[4]);
            float ov = sigmoid_a(g[6]);
            c0 = fmaf(fv, c0, iv * gv);
            float h = ov * tanh_a(c0);
            if (j < HID)
                hnext[((j >> 2) * 2 + 0) * 32 + hp * 4 + (j & 3)] = h;   // even plane
        }
        {
            float iv = sigmoid_a(g[1]);
            float fv = sigmoid_a(g[3]);
            float gv = tanh_a(g[5]);
            float ov = sigmoid_a(g[7]);
            c1 = fmaf(fv, c1, iv * gv);
            float h = ov * tanh_a(c1);
            if (j < HID)
                hnext[((j >> 2) * 2 + 1) * 32 + hp * 4 + (j & 3)] = h;   // odd plane
        }
    };

    int pb = 0;

    // ================= encoder =================
    for (int t = 0; t < S; t++) {
        const float4* cur = hbuf + pb * HBUF_F4;
        float* nxt = (float*)(hbuf + (pb ^ 1) * HBUF_F4);
        gemm(wenc, cur, srcsT[t * BT + b0], srcsT[t * BT + b1]);
        update(nxt);
        pb ^= 1;
        __syncthreads();
    }

    // ================= decoder =================
    stage_c(dWih, dBih, dBhh);
    for (int t = 0; t < T; t++) {
        const float4* cur = hbuf + pb * HBUF_F4;
        float* nxt = (float*)(hbuf + (pb ^ 1) * HBUF_F4);
        gemm(wdec, cur, xdec[b0], xdec[b1]);
        update(nxt);
        pb ^= 1;
        __syncthreads();                      // h_t visible

        if (wrp == 0) {                       // fc: y[b] = h . fcW + fcb
            const float* hf = (const float*)(hbuf + pb * HBUF_F4);
            const int bfc = lane & 15;
            const int hhf = lane >> 4;
            const int hpf = bfc >> 1, parf = bfc & 1;
            float s = 0.f;
            #pragma unroll
            for (int jj2 = 0; jj2 < 25; jj2++) {
                int jq = hhf * 25 + jj2;
                s = fmaf(hf[((jq >> 2) * 2 + parf) * 32 + hpf * 4 + (jq & 3)], fcw[jq], s);
            }
            s += __shfl_xor_sync(0xffffffffu, s, 16);
            if (hhf == 0) {
                float y = s + fcb[0];
                xdec[bfc] = y;
                out[(size_t)(b0g + bfc) * T + t] = y;
            }
        }
        __syncthreads();                      // xdec ready for next step
    }
}

extern "C" void kernel_launch(void* const* d_in, const int* in_sizes, int n_in,
                              void* d_out, int out_size)
{
    const float* source = (const float*)d_in[0];
    const float* eWih = (const float*)d_in[1];
    const float* eWhh = (const float*)d_in[2];
    const float* eBih = (const float*)d_in[3];
    const float* eBhh = (const float*)d_in[4];
    const float* dWih = (const float*)d_in[5];
    const float* dWhh = (const float*)d_in[6];
    const float* dBih = (const float*)d_in[7];
    const float* dBhh = (const float*)d_in[8];
    const float* fcW  = (const float*)d_in[9];
    const float* fcB  = (const float*)d_in[10];
    float* out = (float*)d_out;

    const int B = 2048;
    const int S = in_sizes[0] / B;   // 512
    const int T = out_size   / B;    // 256

    size_t sm = sizeof(float4) * (size_t)(K4N * 4 * JP * 2 + 2 * HBUF_F4)
              + sizeof(float)  * (size_t)(BT + HID + 2)
              + sizeof(float)  * (size_t)BT * S;

    cudaFuncSetAttribute(seq2seq_kernel, cudaFuncAttributeMaxDynamicSharedMemorySize, (int)sm);
    seq2seq_kernel<<<B / BT, NTHREADS, sm>>>(source, eWih, eWhh, eBih, eBhh,
                                             dWih, dWhh, dBih, dBhh, fcW, fcB,
                                             out, S, T);
}